// round 7
// baseline (speedup 1.0000x reference)
#include <cuda_runtime.h>
#include <cuda_fp16.h>
#include <cstdint>

// ---------------- problem dims ----------------
#define NB 64      // batch
#define ND 512     // input dim
#define NH 1024    // hidden
#define NS 512     // seq len
#define NG 4096    // 4*H packed gate columns
#define NK 1536    // D + H
#define NCTA 128
#define NTHR 256
#define KC 256     // K-chunk
#define NCHUNKS 6  // 6*256 = 1536
#define ASTRH 264  // A smem row stride (halves): 256+8 pad
#define WSTRH 1544 // W smem row stride (halves): 1536+8 pad
#define GSTRW 33   // G smem row stride (floats)
#define CSTR 9     // C smem row stride (floats)

// ---------------- smem layout (bytes) ----------------
#define OFF_W 0
#define SZ_W (32 * WSTRH * 2)            // 98816
#define OFF_A (OFF_W + SZ_W)             // 98816
#define SZ_A (2 * 64 * ASTRH * 2)        // 67584
#define OFF_G (OFF_A + SZ_A)             // 166400
#define SZ_G (64 * GSTRW * 4)            // 8448
#define OFF_C (OFF_G + SZ_G)             // 174848
#define SZ_C (64 * CSTR * 4)             // 2304
#define OFF_BS (OFF_C + SZ_C)            // 177152
#define SZ_BS 128
#define SMEM_TOTAL (OFF_BS + SZ_BS)      // 177280 bytes < 227KB

// ---------------- device scratch (static; no runtime alloc allowed) -----
__device__ __half d_Wp[(size_t)NG * NK];            // packed weights [p][k], 12.6 MB
__device__ float d_biasp[NG];                       // packed bias
__device__ __half d_Xh[(size_t)NS * NB * ND];       // x transposed [s][b][d], 33.6 MB
__device__ __half d_Hst[(size_t)(NS + 1) * NB * NH];// H history [t][b][h], 67.2 MB
__device__ unsigned d_bar;                          // grid barrier counter

// ---------------- small helpers ----------------
static __device__ __forceinline__ unsigned sptr(const void* p) {
    return (unsigned)__cvta_generic_to_shared(p);
}
static __device__ __forceinline__ void cpasync16(unsigned dst, const void* src) {
    asm volatile("cp.async.cg.shared.global [%0], [%1], 16;" ::"r"(dst), "l"(src));
}
static __device__ __forceinline__ void cpcommit() {
    asm volatile("cp.async.commit_group;");
}
static __device__ __forceinline__ void cpwait1() {
    asm volatile("cp.async.wait_group 1;");
}
static __device__ __forceinline__ void cpwait0() {
    asm volatile("cp.async.wait_group 0;");
}
static __device__ __forceinline__ void mma16816(float* d, unsigned a0, unsigned a1,
                                                unsigned a2, unsigned a3,
                                                unsigned b0, unsigned b1) {
    asm volatile(
        "mma.sync.aligned.m16n8k16.row.col.f32.f16.f16.f32 "
        "{%0,%1,%2,%3}, {%4,%5,%6,%7}, {%8,%9}, {%0,%1,%2,%3};"
        : "+f"(d[0]), "+f"(d[1]), "+f"(d[2]), "+f"(d[3])
        : "r"(a0), "r"(a1), "r"(a2), "r"(a3), "r"(b0), "r"(b1));
}
static __device__ __forceinline__ float sigmoidf_(float x) {
    return 1.0f / (1.0f + __expf(-x));
}

// ---------------- prep: pack weights + bias, reset barrier ----------------
__global__ void k_pack(const float* __restrict__ Wxi, const float* __restrict__ Whi,
                       const float* __restrict__ bi, const float* __restrict__ Wxf,
                       const float* __restrict__ Whf, const float* __restrict__ bf_,
                       const float* __restrict__ Wxo, const float* __restrict__ Who,
                       const float* __restrict__ bo, const float* __restrict__ Wxc,
                       const float* __restrict__ Whc, const float* __restrict__ bc) {
    const float* Wx[4] = {Wxi, Wxf, Wxo, Wxc};
    const float* Wh[4] = {Whi, Whf, Who, Whc};
    const float* bb[4] = {bi, bf_, bo, bc};
    size_t i = (size_t)blockIdx.x * blockDim.x + threadIdx.x;
    size_t stride = (size_t)gridDim.x * blockDim.x;
    if (i == 0) d_bar = 0u;
    for (size_t idx = i; idx < (size_t)NG * NK; idx += stride) {
        int k = (int)(idx % NK);
        int p = (int)(idx / NK);
        int h = p >> 2, g = p & 3;
        float v = (k < ND) ? Wx[g][(size_t)k * NH + h] : Wh[g][(size_t)(k - ND) * NH + h];
        d_Wp[idx] = __float2half(v);
    }
    for (size_t idx = i; idx < (size_t)NG; idx += stride) {
        int p = (int)idx;
        d_biasp[p] = bb[p & 3][p >> 2];
    }
}

// ---------------- prep: transpose x to [s][b][d] fp16; H0 -> slot 0 ----------
__global__ void k_prep(const float* __restrict__ x, const float* __restrict__ H0) {
    size_t i = (size_t)blockIdx.x * blockDim.x + threadIdx.x;
    size_t stride = (size_t)gridDim.x * blockDim.x;
    for (size_t idx = i; idx < (size_t)NS * NB * ND; idx += stride) {
        size_t d = idx % ND;
        size_t sb = idx / ND;
        size_t b = sb % NB;
        size_t s = sb / NB;
        d_Xh[idx] = __float2half(x[(b * NS + s) * ND + d]);
    }
    for (size_t idx = i; idx < (size_t)NB * NH; idx += stride) {
        d_Hst[idx] = __float2half(H0[idx]);
    }
}

// ---------------- A-chunk loader (cp.async, 64 rows x 256 halves) ------------
static __device__ __forceinline__ void issue_chunk(int s, int c, __half* dstbuf, int tid) {
    const __half* src;
    int pitch;
    if (c < 2) {
        src = d_Xh + (size_t)s * NB * ND + c * KC;
        pitch = ND;
    } else {
        src = d_Hst + (size_t)s * NB * NH + (c - 2) * KC;
        pitch = NH;
    }
#pragma unroll
    for (int j = 0; j < 8; ++j) {
        int q = tid + NTHR * j;   // 0..2047
        int row = q >> 5;         // 0..63
        int seg = q & 31;         // 16B segments within 512B row
        cpasync16(sptr(dstbuf + row * ASTRH + seg * 8),
                  src + (size_t)row * pitch + seg * 8);
    }
}

// ---------------- persistent LSTM main kernel ----------------
__global__ void __launch_bounds__(NTHR, 1)
lstm_main(const float* __restrict__ C0, float* __restrict__ out) {
    extern __shared__ __align__(16) char sm[];
    __half* Wsm = (__half*)(sm + OFF_W);
    __half* Asm = (__half*)(sm + OFF_A);
    float* Gsm = (float*)(sm + OFF_G);
    float* Csm = (float*)(sm + OFF_C);
    float* Bsm = (float*)(sm + OFF_BS);

    const int tid = threadIdx.x;
    const int cta = blockIdx.x;
    const int lane = tid & 31;
    const int wid = tid >> 5;

    // ---- one-time: load this CTA's 32-col weight slice into smem (group #1) ----
    {
        const __half* wsrc = d_Wp + (size_t)(cta * 32) * NK;
#pragma unroll
        for (int j = 0; j < 24; ++j) {
            int q = tid + NTHR * j;     // 6144 segs = 32 rows * 192 segs
            int row = q / 192;
            int seg = q % 192;
            cpasync16(sptr(Wsm + row * WSTRH + seg * 8),
                      wsrc + (size_t)row * NK + seg * 8);
        }
        cpcommit();
    }
    // bias + C0 init
    if (tid < 32) Bsm[tid] = d_biasp[cta * 32 + tid];
    for (int q = tid; q < 512; q += NTHR) {
        int b = q >> 3, hl = q & 7;
        Csm[b * CSTR + hl] = C0[b * NH + cta * 8 + hl];
    }
    __syncthreads();

    // warp tile mapping: mrow in {0,16,32,48}, nbase in {0,16}; 2 n-subtiles each
    const int mrow = (wid & 3) * 16;
    const int nbase = (wid >> 2) * 16;
    const int ra = lane >> 2;
    const int ca = (lane & 3) * 2;
    const int aoff0 = (mrow + ra) * ASTRH + ca;
    const int aoff1 = aoff0 + 8 * ASTRH;
    const int woff0 = (nbase + ra) * WSTRH + ca;
    const int woff1 = (nbase + 8 + ra) * WSTRH + ca;

    float* outHf = out + (size_t)NB * NS;                     // 32768
    float* outCf = out + (size_t)NB * NS + (size_t)NB * NH;   // 98304

    for (int s = 0; s < NS; ++s) {
        // x-chunks can be prefetched before the barrier (independent of H)
        issue_chunk(s, 0, Asm, tid);
        cpcommit();
        issue_chunk(s, 1, Asm + 64 * ASTRH, tid);
        cpcommit();

        if (s > 0) {
            // grid barrier: H_{s-1} writes must be visible before chunks 2..5
            __threadfence();
            __syncthreads();
            if (tid == 0) {
                atomicAdd(&d_bar, 1u);
                const unsigned tgt = (unsigned)NCTA * (unsigned)s;
                while (*(volatile unsigned*)&d_bar < tgt) {
                }
                __threadfence();
            }
            __syncthreads();
        }

        float acc0[4] = {0.f, 0.f, 0.f, 0.f};
        float acc1[4] = {0.f, 0.f, 0.f, 0.f};

#pragma unroll 1
        for (int c = 0; c < NCHUNKS; ++c) {
            if (c < NCHUNKS - 1) cpwait1();
            else cpwait0();
            __syncthreads();
            const __half* Ab = Asm + (c & 1) * 64 * ASTRH;
            const int Kbase = c * KC;
#pragma unroll
            for (int ki = 0; ki < 16; ++ki) {
                const int k = ki * 16;
                unsigned a0 = *(const unsigned*)(Ab + aoff0 + k);
                unsigned a1 = *(const unsigned*)(Ab + aoff1 + k);
                unsigned a2 = *(const unsigned*)(Ab + aoff0 + k + 8);
                unsigned a3 = *(const unsigned*)(Ab + aoff1 + k + 8);
                const int K = Kbase + k;
                unsigned b00 = *(const unsigned*)(Wsm + woff0 + K);
                unsigned b01 = *(const unsigned*)(Wsm + woff0 + K + 8);
                unsigned b10 = *(const unsigned*)(Wsm + woff1 + K);
                unsigned b11 = *(const unsigned*)(Wsm + woff1 + K + 8);
                mma16816(acc0, a0, a1, a2, a3, b00, b01);
                mma16816(acc1, a0, a1, a2, a3, b10, b11);
            }
            __syncthreads();
            if (c < NCHUNKS - 2) {
                issue_chunk(s, c + 2, Asm + (c & 1) * 64 * ASTRH, tid);
                cpcommit();
            }
        }

        // ---- epilogue: fragments -> Gsm ----
        {
            const int r0 = mrow + ra;
            const int c0 = nbase + ca;
            const int c1 = nbase + 8 + ca;
            Gsm[r0 * GSTRW + c0] = acc0[0];
            Gsm[r0 * GSTRW + c0 + 1] = acc0[1];
            Gsm[(r0 + 8) * GSTRW + c0] = acc0[2];
            Gsm[(r0 + 8) * GSTRW + c0 + 1] = acc0[3];
            Gsm[r0 * GSTRW + c1] = acc1[0];
            Gsm[r0 * GSTRW + c1 + 1] = acc1[1];
            Gsm[(r0 + 8) * GSTRW + c1] = acc1[2];
            Gsm[(r0 + 8) * GSTRW + c1 + 1] = acc1[3];
        }
        __syncthreads();

        // ---- gates: each thread handles (b, 2 hidden units) ----
        {
            const int b = tid & 63;
            const int h2 = (tid >> 6) * 2;  // 0,2,4,6
            float hn[2], cn[2];
#pragma unroll
            for (int u = 0; u < 2; ++u) {
                const int hl = h2 + u;
                const float* Gr = Gsm + b * GSTRW + 4 * hl;
                float gi = Gr[0] + Bsm[4 * hl + 0];
                float gf = Gr[1] + Bsm[4 * hl + 1];
                float go = Gr[2] + Bsm[4 * hl + 2];
                float gc = Gr[3] + Bsm[4 * hl + 3];
                float iv = sigmoidf_(gi);
                float fv = sigmoidf_(gf);
                float ov = sigmoidf_(go);
                float cv = tanhf(gc);
                float cp = Csm[b * CSTR + hl];
                cn[u] = fv * cp + iv * cv;
                hn[u] = ov * tanhf(cn[u]);
                Csm[b * CSTR + hl] = cn[u];
            }
            __half2 hh = __floats2half2_rn(hn[0], hn[1]);
            *(__half2*)(d_Hst + (size_t)(s + 1) * NB * NH + (size_t)b * NH + cta * 8 + h2) = hh;
            if (s == NS - 1) {
                const int hg = cta * 8 + h2;
                outHf[(size_t)b * NH + hg] = hn[0];
                outHf[(size_t)b * NH + hg + 1] = hn[1];
                outCf[(size_t)b * NH + hg] = cn[0];
                outCf[(size_t)b * NH + hg + 1] = cn[1];
            }
        }
        __syncthreads();
    }
}

// ---------------- final GEMV: pred[b][s] = dot(H_{s+1}[b], fcW) + fc_b -------
__global__ void k_pred(const float* __restrict__ fcW, const float* __restrict__ fcb,
                       float* __restrict__ out) {
    const int w = blockIdx.x * (blockDim.x >> 5) + (threadIdx.x >> 5);  // 0..32767
    const int lane = threadIdx.x & 31;
    const int b = w >> 9;
    const int s = w & 511;
    const __half2* hp = (const __half2*)(d_Hst + (size_t)(s + 1) * NB * NH + (size_t)b * NH);
    const float2* wp = (const float2*)fcW;
    float acc = 0.f;
#pragma unroll 4
    for (int j = lane; j < NH / 2; j += 32) {
        __half2 h2 = hp[j];
        float2 wv = wp[j];
        acc += __low2float(h2) * wv.x + __high2float(h2) * wv.y;
    }
#pragma unroll
    for (int o = 16; o; o >>= 1) acc += __shfl_xor_sync(0xffffffffu, acc, o);
    if (lane == 0) out[(size_t)b * NS + s] = acc + fcb[0];
}

// ---------------- launch ----------------
extern "C" void kernel_launch(void* const* d_in, const int* in_sizes, int n_in,
                              void* d_out, int out_size) {
    (void)in_sizes;
    (void)n_in;
    (void)out_size;
    const float* x = (const float*)d_in[0];
    const float* H0 = (const float*)d_in[1];
    const float* C0 = (const float*)d_in[2];
    const float* Wxi = (const float*)d_in[3];
    const float* Whi = (const float*)d_in[4];
    const float* bi = (const float*)d_in[5];
    const float* Wxf = (const float*)d_in[6];
    const float* Whf = (const float*)d_in[7];
    const float* bf_ = (const float*)d_in[8];
    const float* Wxo = (const float*)d_in[9];
    const float* Who = (const float*)d_in[10];
    const float* bo = (const float*)d_in[11];
    const float* Wxc = (const float*)d_in[12];
    const float* Whc = (const float*)d_in[13];
    const float* bc = (const float*)d_in[14];
    const float* fcW = (const float*)d_in[15];
    const float* fcb = (const float*)d_in[16];
    float* out = (float*)d_out;

    cudaFuncSetAttribute(lstm_main, cudaFuncAttributeMaxDynamicSharedMemorySize, SMEM_TOTAL);

    k_pack<<<2048, 256>>>(Wxi, Whi, bi, Wxf, Whf, bf_, Wxo, Who, bo, Wxc, Whc, bc);
    k_prep<<<4096, 256>>>(x, H0);
    lstm_main<<<NCTA, NTHR, SMEM_TOTAL>>>(C0, out);
    k_pred<<<4096, 256>>>(fcW, fcb, out);
}

// round 9
// speedup vs baseline: 1.2064x; 1.2064x over previous
#include <cuda_runtime.h>
#include <cuda_fp16.h>
#include <cstdint>

// ---------------- problem dims ----------------
#define NB 64      // batch
#define ND 512     // input dim
#define NH 1024    // hidden
#define NS 512     // seq len
#define NGP 4096   // packed gate columns (4*H)
#define NCTA 128
#define NTHR 256

// ---------------- lstm_main smem layout ----------------
#define CHSTR 136                       // halves per chunk row (128 + 8 pad)
#define CHBYTES (64 * CHSTR * 2)        // 17408 per warp chunk
#define OFF_P (8 * CHBYTES)             // 139264
#define PWSTR 65                        // floats per lane slot in partial buf
#define PWFL (32 * PWSTR)               // floats per warp partial buf (2080)
#define SMEM_MAIN (OFF_P + 8 * PWFL * 4)  // 139264 + 66560 = 205824

// ---------------- xproj smem layout ----------------
#define XSTR 72                          // halves per row (64 + 8 pad)
#define XAB (128 * XSTR * 2)             // 18432 per buffer
#define SMEM_XP (4 * XAB)                // 73728: A0,A1,B0,B1

// ---------------- device scratch (static; no runtime alloc) ----------------
__device__ __half d_Wh[(size_t)NGP * NH];          // packed Wh [p][k], 8.4 MB
__device__ __half d_Wx[(size_t)NGP * ND];          // packed Wx [p][k], 4.2 MB
__device__ float d_bias[NGP];
__device__ __half d_Xh[(size_t)NS * NB * ND];      // x [s][b][d] fp16, 33.6 MB
__device__ __half d_XP[(size_t)NS * NB * NGP];     // x_proj [s*64+b][p] fp16, 268 MB
__device__ __half d_Hst[(size_t)(NS + 1) * NB * NH]; // H history [t][b][h], 67 MB
__device__ unsigned d_bar;                         // grid barrier

// ---------------- helpers ----------------
static __device__ __forceinline__ unsigned sptr(const void* p) {
    return (unsigned)__cvta_generic_to_shared(p);
}
static __device__ __forceinline__ void cpasync16(unsigned dst, const void* src) {
    asm volatile("cp.async.cg.shared.global [%0], [%1], 16;" ::"r"(dst), "l"(src));
}
static __device__ __forceinline__ void cpcommit() {
    asm volatile("cp.async.commit_group;");
}
static __device__ __forceinline__ void cpwait0() {
    asm volatile("cp.async.wait_group 0;");
}
static __device__ __forceinline__ void cpwait1() {
    asm volatile("cp.async.wait_group 1;");
}
static __device__ __forceinline__ void mma16816(float* d, unsigned a0, unsigned a1,
                                                unsigned a2, unsigned a3,
                                                unsigned b0, unsigned b1) {
    asm volatile(
        "mma.sync.aligned.m16n8k16.row.col.f32.f16.f16.f32 "
        "{%0,%1,%2,%3}, {%4,%5,%6,%7}, {%8,%9}, {%0,%1,%2,%3};"
        : "+f"(d[0]), "+f"(d[1]), "+f"(d[2]), "+f"(d[3])
        : "r"(a0), "r"(a1), "r"(a2), "r"(a3), "r"(b0), "r"(b1));
}
static __device__ __forceinline__ float sigmoidf_(float x) {
    return 1.0f / (1.0f + __expf(-x));
}

// ---------------- pack weights (transpose to [p][k], fp16) + bias -----------
__global__ void k_pack(const float* __restrict__ Wxi, const float* __restrict__ Whi,
                       const float* __restrict__ bi, const float* __restrict__ Wxf,
                       const float* __restrict__ Whf, const float* __restrict__ bf_,
                       const float* __restrict__ Wxo, const float* __restrict__ Who,
                       const float* __restrict__ bo, const float* __restrict__ Wxc,
                       const float* __restrict__ Whc, const float* __restrict__ bc) {
    const float* Wx[4] = {Wxi, Wxf, Wxo, Wxc};
    const float* Wh[4] = {Whi, Whf, Who, Whc};
    const float* bb[4] = {bi, bf_, bo, bc};
    size_t i = (size_t)blockIdx.x * blockDim.x + threadIdx.x;
    size_t stride = (size_t)gridDim.x * blockDim.x;
    if (i == 0) d_bar = 0u;
    for (size_t idx = i; idx < (size_t)NGP * NH; idx += stride) {
        int k = (int)(idx % NH);
        int p = (int)(idx / NH);
        d_Wh[idx] = __float2half(Wh[p & 3][(size_t)k * NH + (p >> 2)]);
    }
    for (size_t idx = i; idx < (size_t)NGP * ND; idx += stride) {
        int k = (int)(idx % ND);
        int p = (int)(idx / ND);
        d_Wx[idx] = __float2half(Wx[p & 3][(size_t)k * NH + (p >> 2)]);
    }
    for (size_t idx = i; idx < (size_t)NGP; idx += stride) {
        d_bias[idx] = bb[idx & 3][idx >> 2];
    }
}

// ---------------- prep: x -> [s][b][d] fp16; H0 -> Hst[0] --------------------
__global__ void k_prep(const float* __restrict__ x, const float* __restrict__ H0) {
    size_t i = (size_t)blockIdx.x * blockDim.x + threadIdx.x;
    size_t stride = (size_t)gridDim.x * blockDim.x;
    for (size_t idx = i; idx < (size_t)NS * NB * ND; idx += stride) {
        size_t d = idx % ND;
        size_t sb = idx / ND;
        size_t b = sb % NB;
        size_t s = sb / NB;
        d_Xh[idx] = __float2half(x[(b * NS + s) * ND + d]);
    }
    for (size_t idx = i; idx < (size_t)NB * NH; idx += stride) {
        d_Hst[idx] = __float2half(H0[idx]);
    }
}

// ---------------- xproj GEMM: XP[m][p] = sum_d Xh[m][d] * Wx[p][d] -----------
// M=32768 (m = s*64+b), N=4096, K=512. BM=128, BN=128, BK=64, 8 warps @ 32x64.
__global__ void __launch_bounds__(NTHR, 1) k_xproj() {
    extern __shared__ __align__(16) char sm[];
    const int tid = threadIdx.x;
    const int lane = tid & 31;
    const int wid = tid >> 5;
    const int bx = blockIdx.x;  // m-tile (0..255)
    const int by = blockIdx.y;  // n-tile (0..31)

    const int mw = wid >> 1;          // 0..3
    const int nw = wid & 1;           // 0..1
    const int mbase = mw * 32;
    const int nbase = nw * 64;
    const int ra = lane >> 2;
    const int ca = (lane & 3) * 2;

    const __half* Asrc = d_Xh + (size_t)(bx * 128) * ND;
    const __half* Bsrc = d_Wx + (size_t)(by * 128) * ND;

    // load chunk kc into buffer (kc&1)
    auto load = [&](int kc) {
        char* Ab = sm + (kc & 1) * XAB;
        char* Bb = sm + 2 * XAB + (kc & 1) * XAB;
#pragma unroll
        for (int j = 0; j < 4; ++j) {
            int q = tid + NTHR * j;  // 0..1023
            int row = q >> 3;
            int seg = q & 7;
            cpasync16(sptr(Ab + (row * XSTR + seg * 8) * 2),
                      Asrc + (size_t)row * ND + kc * 64 + seg * 8);
        }
#pragma unroll
        for (int j = 0; j < 4; ++j) {
            int q = tid + NTHR * j;
            int row = q >> 3;
            int seg = q & 7;
            cpasync16(sptr(Bb + (row * XSTR + seg * 8) * 2),
                      Bsrc + (size_t)row * ND + kc * 64 + seg * 8);
        }
        cpcommit();
    };

    float acc[2][8][4];
#pragma unroll
    for (int mi = 0; mi < 2; ++mi)
#pragma unroll
        for (int n8 = 0; n8 < 8; ++n8)
#pragma unroll
            for (int t = 0; t < 4; ++t) acc[mi][n8][t] = 0.f;

    load(0);
#pragma unroll 1
    for (int kc = 0; kc < 8; ++kc) {
        if (kc < 7) load(kc + 1);
        if (kc < 7) cpwait1();
        else cpwait0();
        __syncthreads();
        const __half* Ab = (const __half*)(sm + (kc & 1) * XAB);
        const __half* Bb = (const __half*)(sm + 2 * XAB + (kc & 1) * XAB);
#pragma unroll
        for (int k16 = 0; k16 < 4; ++k16) {
            unsigned a[2][4];
#pragma unroll
            for (int mi = 0; mi < 2; ++mi) {
                int base = (mbase + mi * 16 + ra) * XSTR + k16 * 16 + ca;
                a[mi][0] = *(const unsigned*)(Ab + base);
                a[mi][1] = *(const unsigned*)(Ab + base + 8 * XSTR);
                a[mi][2] = *(const unsigned*)(Ab + base + 8);
                a[mi][3] = *(const unsigned*)(Ab + base + 8 * XSTR + 8);
            }
#pragma unroll
            for (int n8 = 0; n8 < 8; ++n8) {
                int wb = (nbase + n8 * 8 + ra) * XSTR + k16 * 16 + ca;
                unsigned b0 = *(const unsigned*)(Bb + wb);
                unsigned b1 = *(const unsigned*)(Bb + wb + 8);
#pragma unroll
                for (int mi = 0; mi < 2; ++mi)
                    mma16816(acc[mi][n8], a[mi][0], a[mi][1], a[mi][2], a[mi][3], b0, b1);
            }
        }
        __syncthreads();
    }

    // epilogue: fp16 store
#pragma unroll
    for (int mi = 0; mi < 2; ++mi) {
#pragma unroll
        for (int n8 = 0; n8 < 8; ++n8) {
            int m0 = bx * 128 + mbase + mi * 16 + ra;
            int c0 = by * 128 + nbase + n8 * 8 + ca;
            *(__half2*)(d_XP + (size_t)m0 * NGP + c0) =
                __floats2half2_rn(acc[mi][n8][0], acc[mi][n8][1]);
            *(__half2*)(d_XP + (size_t)(m0 + 8) * NGP + c0) =
                __floats2half2_rn(acc[mi][n8][2], acc[mi][n8][3]);
        }
    }
}

// ---------------- persistent LSTM recurrence ----------------
// 128 CTAs x 256 thr. CTA owns 32 packed cols (8 hidden units). K=1024 (H only).
// Warp w holds B-frags for K in [w*128, w*128+128) in registers; full 64Mx32N.
__global__ void __launch_bounds__(NTHR, 1) lstm_main(const float* __restrict__ C0,
                                                     float* __restrict__ out) {
    extern __shared__ __align__(16) char sm[];
    const int tid = threadIdx.x;
    const int lane = tid & 31;
    const int wid = tid >> 5;  // = kq (0..7)
    const int cta = blockIdx.x;
    const int pbase = cta * 32;
    const int hbase = cta * 8;
    const int ra = lane >> 2;
    const int ca = (lane & 3) * 2;

    // ---- load B fragments into registers (once) ----
    unsigned Bf[4][8][2];
#pragma unroll
    for (int n8 = 0; n8 < 4; ++n8) {
        const __half* wp = d_Wh + (size_t)(pbase + n8 * 8 + ra) * NH + wid * 128 + ca;
#pragma unroll
        for (int k16 = 0; k16 < 8; ++k16) {
            Bf[n8][k16][0] = *(const unsigned*)(wp + k16 * 16);
            Bf[n8][k16][1] = *(const unsigned*)(wp + k16 * 16 + 8);
        }
    }

    // ---- gate-thread identity: (b, 2 hidden units) fixed for whole run ----
    const int gb = tid & 63;
    const int gh2 = (tid >> 6) * 2;  // 0,2,4,6
    float bias8[8];
#pragma unroll
    for (int j = 0; j < 8; ++j) bias8[j] = d_bias[pbase + gh2 * 4 + j];
    float Creg0 = C0[(size_t)gb * NH + hbase + gh2];
    float Creg1 = C0[(size_t)gb * NH + hbase + gh2 + 1];

    // gather index precompute (degree-2 banks at worst)
    int sl[8], gi_[8];
#pragma unroll
    for (int j = 0; j < 8; ++j) {
        int n = gh2 * 4 + j;
        sl[j] = (gb & 7) * 4 + ((n >> 1) & 3);
        gi_[j] = ((gb >> 4) * 4 + (n >> 3)) * 4 + ((gb >> 3) & 1) * 2 + (n & 1);
    }

    char* mych = sm + wid * CHBYTES;
    const unsigned mychs = sptr(mych);
    float* Pbuf = (float*)(sm + OFF_P);
    float* pw = Pbuf + wid * PWFL + lane * PWSTR;

    float* outHf = out + (size_t)NB * NS;
    float* outCf = outHf + (size_t)NB * NH;

    for (int s = 0; s < NS; ++s) {
        if (s > 0) {
            __threadfence();
            __syncthreads();
            if (tid == 0) {
                atomicAdd(&d_bar, 1u);
                const unsigned tgt = (unsigned)NCTA * (unsigned)s;
                while (*(volatile unsigned*)&d_bar < tgt) {
                }
                __threadfence();
            }
            __syncthreads();
        }

        // ---- per-warp self-contained load of its K-chunk of H_{s} ----
        {
            const __half* src = d_Hst + (size_t)s * NB * NH + wid * 128;
#pragma unroll
            for (int j = 0; j < 32; ++j) {
                int q = j * 32 + lane;  // 0..1023
                int row = q >> 4;
                int seg = q & 15;
                cpasync16(mychs + (unsigned)(row * CHSTR + seg * 8) * 2,
                          src + (size_t)row * NH + seg * 8);
            }
            cpcommit();
            cpwait0();
            __syncwarp();
        }

        // ---- MMA: 64M x 32N x 128K per warp ----
        float acc[4][4][4];
#pragma unroll
        for (int mi = 0; mi < 4; ++mi)
#pragma unroll
            for (int n8 = 0; n8 < 4; ++n8)
#pragma unroll
                for (int t = 0; t < 4; ++t) acc[mi][n8][t] = 0.f;

        const __half* Ab = (const __half*)mych;
#pragma unroll
        for (int k16 = 0; k16 < 8; ++k16) {
            unsigned a[4][4];
#pragma unroll
            for (int mi = 0; mi < 4; ++mi) {
                int base = (mi * 16 + ra) * CHSTR + k16 * 16 + ca;
                a[mi][0] = *(const unsigned*)(Ab + base);
                a[mi][1] = *(const unsigned*)(Ab + base + 8 * CHSTR);
                a[mi][2] = *(const unsigned*)(Ab + base + 8);
                a[mi][3] = *(const unsigned*)(Ab + base + 8 * CHSTR + 8);
            }
#pragma unroll
            for (int mi = 0; mi < 4; ++mi)
#pragma unroll
                for (int n8 = 0; n8 < 4; ++n8)
                    mma16816(acc[mi][n8], a[mi][0], a[mi][1], a[mi][2], a[mi][3],
                             Bf[n8][k16][0], Bf[n8][k16][1]);
        }

        // ---- write partials ([w][lane][i], conflict-free) ----
#pragma unroll
        for (int mi = 0; mi < 4; ++mi)
#pragma unroll
            for (int n8 = 0; n8 < 4; ++n8)
#pragma unroll
                for (int t = 0; t < 4; ++t)
                    pw[(mi * 4 + n8) * 4 + t] = acc[mi][n8][t];
        __syncthreads();

        // ---- gather 8-way K-reduction + x_proj + gates ----
        {
            float g[8];
#pragma unroll
            for (int j = 0; j < 8; ++j) {
                float v = 0.f;
                const int off = sl[j] * PWSTR + gi_[j];
#pragma unroll
                for (int w = 0; w < 8; ++w) v += Pbuf[w * PWFL + off];
                g[j] = v;
            }
            const __half* xp = d_XP + ((size_t)s * NB + gb) * NGP + pbase + gh2 * 4;
            uint4 xr = *(const uint4*)xp;
            const __half2* xh = (const __half2*)&xr;
            float xv[8];
#pragma unroll
            for (int t = 0; t < 4; ++t) {
                xv[2 * t] = __low2float(xh[t]);
                xv[2 * t + 1] = __high2float(xh[t]);
            }
            float hn0, hn1, cn0, cn1;
            {
                float gii = g[0] + bias8[0] + xv[0];
                float gff = g[1] + bias8[1] + xv[1];
                float goo = g[2] + bias8[2] + xv[2];
                float gcc = g[3] + bias8[3] + xv[3];
                float iv = sigmoidf_(gii), fv = sigmoidf_(gff);
                float ov = sigmoidf_(goo), cv = tanhf(gcc);
                cn0 = fv * Creg0 + iv * cv;
                hn0 = ov * tanhf(cn0);
                Creg0 = cn0;
            }
            {
                float gii = g[4] + bias8[4] + xv[4];
                float gff = g[5] + bias8[5] + xv[5];
                float goo = g[6] + bias8[6] + xv[6];
                float gcc = g[7] + bias8[7] + xv[7];
                float iv = sigmoidf_(gii), fv = sigmoidf_(gff);
                float ov = sigmoidf_(goo), cv = tanhf(gcc);
                cn1 = fv * Creg1 + iv * cv;
                hn1 = ov * tanhf(cn1);
                Creg1 = cn1;
            }
            *(__half2*)(d_Hst + (size_t)(s + 1) * NB * NH + (size_t)gb * NH + hbase + gh2) =
                __floats2half2_rn(hn0, hn1);
            if (s == NS - 1) {
                outHf[(size_t)gb * NH + hbase + gh2] = hn0;
                outHf[(size_t)gb * NH + hbase + gh2 + 1] = hn1;
                outCf[(size_t)gb * NH + hbase + gh2] = cn0;
                outCf[(size_t)gb * NH + hbase + gh2 + 1] = cn1;
            }
        }
    }
}

// ---------------- final GEMV: pred[b][s] ----------------
__global__ void k_pred(const float* __restrict__ fcW, const float* __restrict__ fcb,
                       float* __restrict__ out) {
    const int w = blockIdx.x * (blockDim.x >> 5) + (threadIdx.x >> 5);  // 0..32767
    const int lane = threadIdx.x & 31;
    const int b = w >> 9;
    const int s = w & 511;
    const __half2* hp = (const __half2*)(d_Hst + (size_t)(s + 1) * NB * NH + (size_t)b * NH);
    const float2* wp = (const float2*)fcW;
    float acc = 0.f;
#pragma unroll 4
    for (int j = lane; j < NH / 2; j += 32) {
        __half2 h2 = hp[j];
        float2 wv = wp[j];
        acc += __low2float(h2) * wv.x + __high2float(h2) * wv.y;
    }
#pragma unroll
    for (int o = 16; o; o >>= 1) acc += __shfl_xor_sync(0xffffffffu, acc, o);
    if (lane == 0) out[(size_t)b * NS + s] = acc + fcb[0];
}

// ---------------- launch ----------------
extern "C" void kernel_launch(void* const* d_in, const int* in_sizes, int n_in,
                              void* d_out, int out_size) {
    (void)in_sizes;
    (void)n_in;
    (void)out_size;
    const float* x = (const float*)d_in[0];
    const float* H0 = (const float*)d_in[1];
    const float* C0 = (const float*)d_in[2];
    const float* Wxi = (const float*)d_in[3];
    const float* Whi = (const float*)d_in[4];
    const float* bi = (const float*)d_in[5];
    const float* Wxf = (const float*)d_in[6];
    const float* Whf = (const float*)d_in[7];
    const float* bf_ = (const float*)d_in[8];
    const float* Wxo = (const float*)d_in[9];
    const float* Who = (const float*)d_in[10];
    const float* bo = (const float*)d_in[11];
    const float* Wxc = (const float*)d_in[12];
    const float* Whc = (const float*)d_in[13];
    const float* bc = (const float*)d_in[14];
    const float* fcW = (const float*)d_in[15];
    const float* fcb = (const float*)d_in[16];
    float* out = (float*)d_out;

    cudaFuncSetAttribute(lstm_main, cudaFuncAttributeMaxDynamicSharedMemorySize, SMEM_MAIN);
    cudaFuncSetAttribute(k_xproj, cudaFuncAttributeMaxDynamicSharedMemorySize, SMEM_XP);

    k_pack<<<2048, 256>>>(Wxi, Whi, bi, Wxf, Whf, bf_, Wxo, Who, bo, Wxc, Whc, bc);
    k_prep<<<4096, 256>>>(x, H0);
    {
        dim3 g(256, 32);
        k_xproj<<<g, NTHR, SMEM_XP>>>();
    }
    lstm_main<<<NCTA, NTHR, SMEM_MAIN>>>(C0, out);
    k_pred<<<4096, 256>>>(fcW, fcb, out);
}